// round 13
// baseline (speedup 1.0000x reference)
#include <cuda_runtime.h>
#include <cuda_fp16.h>
#include <math.h>
#include <stdint.h>

// Problem constants
#define BD   4
#define LD   8192
#define CD   256
#define HID  2048
#define NS   8
#define EPSL 1e-5f

// ---------------- scratch (__device__ globals; no allocations) ----------------
__device__ __align__(16) __half h_src[BD * LD * CD];
__device__ __align__(16) __half h_Wq[CD * CD];
__device__ __align__(16) __half h_Wkv[CD * 2 * CD];     // interleaved [k][Wk|Wv]
__device__ __align__(16) __half h_Wl[CD * CD];
__device__ __align__(16) __half h_Wql[CD * CD];         // Wq @ Wl
__device__ __align__(16) __half h_W1[2 * CD * HID];
__device__ __align__(16) __half h_W2[HID * CD];
__device__ __align__(16) __half h_KV[BD * LD * 2 * CD]; // cols 0-255 exp(K), 256-511 V
__device__ __align__(16) __half h_Sn[BD * CD * CD];
__device__ __align__(16) __half h_Mm[BD * CD * CD];
__device__ __align__(16) __half h_attn[BD * LD * CD];   // reused as fp16 tmp2 after FFN1
__device__ __align__(16) __half h_hidden[BD * LD * HID];
__device__ float g_Spart[BD * NS * CD * CD];
__device__ float g_colsum[BD * CD];
__device__ float g_psum[BD * CD * 8];

// ---------------- helpers ----------------
__device__ __forceinline__ void mma_f16(float* c, const uint32_t* a, const uint32_t* b) {
    asm volatile(
        "mma.sync.aligned.m16n8k16.row.col.f32.f16.f16.f32 "
        "{%0,%1,%2,%3}, {%4,%5,%6,%7}, {%8,%9}, {%0,%1,%2,%3};"
        : "+f"(c[0]), "+f"(c[1]), "+f"(c[2]), "+f"(c[3])
        : "r"(a[0]), "r"(a[1]), "r"(a[2]), "r"(a[3]), "r"(b[0]), "r"(b[1]));
}
__device__ __forceinline__ void ldsm4(uint32_t* r, uint32_t a) {
    asm volatile("ldmatrix.sync.aligned.m8n8.x4.shared.b16 {%0,%1,%2,%3}, [%4];"
                 : "=r"(r[0]), "=r"(r[1]), "=r"(r[2]), "=r"(r[3]) : "r"(a));
}
__device__ __forceinline__ void ldsm4t(uint32_t* r, uint32_t a) {
    asm volatile("ldmatrix.sync.aligned.m8n8.x4.trans.shared.b16 {%0,%1,%2,%3}, [%4];"
                 : "=r"(r[0]), "=r"(r[1]), "=r"(r[2]), "=r"(r[3]) : "r"(a));
}
__device__ __forceinline__ void cpasync16(uint32_t dst, const void* src) {
    asm volatile("cp.async.cg.shared.global [%0], [%1], 16;" :: "r"(dst), "l"(src));
}
__device__ __forceinline__ void cp_commit() {
    asm volatile("cp.async.commit_group;" ::: "memory");
}

// ---------------- fp16 GEMM tiling ----------------
// CTA tile 128x128x64; 8 warps (2 m x 4 n), warp tile 64x32.
// SMEM (halves), 16B-chunk xor swizzle, all LDSM/STS conflict-free:
//   A: byte(m,k) = m*128 + (((k/8) ^ (m&7))*16 + (k&7)*2)   (128 rows x 64 k)
//   B: byte(k,n) = k*256 + (((n/8) ^ (k&7))*16 + (n&7)*2)   (64 k-rows x 128 n)
#define BKH 64
#define ASTG 16384
#define STAGE 32768
#define SMEM_ASYNC (3 * STAGE)    // 98304
#define SMEM_T     (2 * STAGE)    // 65536

// Pipelined compute over one 64-k smem stage (8 warps). bf double-buffered.
#define COMPUTE_STAGE(Ab0, Bb0)                                                 \
    do {                                                                        \
        uint32_t bf[2][8];                                                      \
        ldsm4t(bf[0],     (Bb0) + bXor0);                                       \
        ldsm4t(bf[0] + 4, (Bb0) + bXor1);                                       \
        _Pragma("unroll")                                                       \
        for (int st = 0; st < 4; st++) {                                        \
            uint32_t af[4][4];                                                  \
            _Pragma("unroll")                                                   \
            for (int i = 0; i < 4; i++)                                         \
                ldsm4(af[i], (Ab0) + i * 2048 +                                 \
                      ((((uint32_t)st * 2 + aSel) ^ aXor) << 4));               \
            if (st < 3) {                                                       \
                ldsm4t(bf[(st + 1) & 1],     (Bb0) + (st + 1) * 4096 + bXor0);  \
                ldsm4t(bf[(st + 1) & 1] + 4, (Bb0) + (st + 1) * 4096 + bXor1);  \
            }                                                                   \
            const uint32_t* bc = bf[st & 1];                                    \
            _Pragma("unroll")                                                   \
            for (int i = 0; i < 4; i++) {                                       \
                mma_f16(acc[i][0], af[i], bc);                                  \
                mma_f16(acc[i][1], af[i], bc + 2);                              \
                mma_f16(acc[i][2], af[i], bc + 4);                              \
                mma_f16(acc[i][3], af[i], bc + 6);                              \
            }                                                                   \
        }                                                                       \
    } while (0)

#define DECLARE_FRAG_CONSTS                                                     \
    const uint32_t aRow = lane & 15, aSel = lane >> 4, aXor = aRow & 7;         \
    const uint32_t aByteBase = (uint32_t)(wm * 64 + aRow) * 128;                \
    const uint32_t r8 = lane & 7, g8 = lane >> 3;                               \
    const uint32_t bRowByte = ((g8 & 1) * 8 + r8) * 256;                        \
    const uint32_t bXor0 = (((uint32_t)wn * 4 + (g8 >> 1)) ^ r8) << 4;          \
    const uint32_t bXor1 = (((uint32_t)wn * 4 + 2 + (g8 >> 1)) ^ r8) << 4;

// ============ cp.async pipelined fp16 GEMM (A row-major / concat) ============
// EPI: 0 store; 1 +bias; 2 +bias+GELU. OUTH: 1 = __half out, 0 = float out.
template <int AMODE, int EPI, int OUTH>
__global__ void __launch_bounds__(256, 2)
hgemm_async(const __half* __restrict__ A, const __half* __restrict__ A2,
            const __half* __restrict__ Bm, const float* __restrict__ bias,
            void* __restrict__ Cmat,
            int Kd, int lda, int ldb, int ldc,
            long long sA, long long sB, long long sC)
{
    extern __shared__ char smc[];
    const uint32_t sbase = (uint32_t)__cvta_generic_to_shared(smc);
    const int tid = threadIdx.x;
    const int wid = tid >> 5, lane = tid & 31;
    const int wm = wid >> 2, wn = wid & 3;
    const int gid = lane >> 2, tig = lane & 3;

    const int b = blockIdx.z;
    const __half* Ab = A + (long long)b * sA;
    const __half* Bb = Bm + (long long)b * sB;
    const int T = Kd / BKH;
    const int m0 = blockIdx.y * 128;
    const int n0 = blockIdx.x * 128;

    DECLARE_FRAG_CONSTS

    auto issue = [&](int it) {
        const uint32_t Abase = sbase + (uint32_t)(it % 3) * STAGE;
        const uint32_t Bbase = Abase + ASTG;
        const int kt = it * BKH;
#pragma unroll
        for (int j = 0; j < 4; j++) {
            const int idx = tid + 256 * j;
            const int m = idx >> 3, f = idx & 7;
            const int kk = kt + f * 8;
            const __half* src;
            if (AMODE == 2)
                src = (kk < CD) ? Ab + (size_t)(m0 + m) * CD + kk
                                : A2 + (size_t)(m0 + m) * CD + (kk - CD);
            else
                src = Ab + (size_t)(m0 + m) * lda + kk;
            cpasync16(Abase + (uint32_t)(m * 128 + ((f ^ (m & 7)) << 4)), src);
        }
#pragma unroll
        for (int j = 0; j < 4; j++) {
            const int idx = tid + 256 * j;
            const int k = idx >> 4, c = idx & 15;
            const __half* src = Bb + (size_t)(kt + k) * ldb + n0 + c * 8;
            cpasync16(Bbase + (uint32_t)(k * 256 + ((c ^ (k & 7)) << 4)), src);
        }
        cp_commit();
    };

    float acc[4][4][4];
#pragma unroll
    for (int i = 0; i < 4; i++)
#pragma unroll
        for (int j = 0; j < 4; j++)
#pragma unroll
            for (int e = 0; e < 4; e++) acc[i][j][e] = 0.0f;

    issue(0);
    if (T > 1) issue(1);

    for (int it = 0; it < T; ++it) {
        if (it + 1 < T) asm volatile("cp.async.wait_group 1;" ::: "memory");
        else            asm volatile("cp.async.wait_group 0;" ::: "memory");
        __syncthreads();
        if (it + 2 < T) issue(it + 2);

        const uint32_t Ab0 = sbase + (uint32_t)(it % 3) * STAGE + aByteBase;
        const uint32_t Bb0 = sbase + (uint32_t)(it % 3) * STAGE + ASTG + bRowByte;
        COMPUTE_STAGE(Ab0, Bb0);
    }

    // ---- epilogue ----
#pragma unroll
    for (int i = 0; i < 4; i++) {
        const int rbase = m0 + wm * 64 + i * 16 + gid;
#pragma unroll
        for (int j = 0; j < 4; j++) {
            const int cn = n0 + wn * 32 + j * 8 + tig * 2;
            float bia0 = 0.f, bia1 = 0.f;
            if (EPI >= 1) { bia0 = bias[cn]; bia1 = bias[cn + 1]; }
#pragma unroll
            for (int h = 0; h < 2; h++) {
                const int row = rbase + h * 8;
                float v0 = acc[i][j][2 * h + 0] + bia0;
                float v1 = acc[i][j][2 * h + 1] + bia1;
                if (EPI == 2) {
                    v0 = 0.5f * v0 * (1.0f + erff(v0 * 0.70710678118654752f));
                    v1 = 0.5f * v1 * (1.0f + erff(v1 * 0.70710678118654752f));
                }
                if (OUTH) {
                    __half2 hv = __floats2half2_rn(v0, v1);
                    *(__half2*)((__half*)Cmat + (long long)b * sC + (size_t)row * ldc + cn) = hv;
                } else {
                    float2 fv; fv.x = v0; fv.y = v1;
                    *(float2*)((float*)Cmat + (long long)b * sC + (size_t)row * ldc + cn) = fv;
                }
            }
        }
    }
}

// ============ row-major fp32-A GEMM (register-staged, converts A to fp16) =====
// Used for the KV projection: A = target (fp32), fused exp on columns < CD.
// EPI: 3 = exp on cn<CD; 0 = plain.
template <int EPI>
__global__ void __launch_bounds__(256)
hgemm_rm32(const float* __restrict__ Af, const __half* __restrict__ Bb,
           __half* __restrict__ Cmat,
           int Kd, int lda, int ldb, int ldc, long long sA, long long sC)
{
    extern __shared__ char smc[];
    const uint32_t sbase = (uint32_t)__cvta_generic_to_shared(smc);
    const int tid = threadIdx.x;
    const int wid = tid >> 5, lane = tid & 31;
    const int wm = wid >> 2, wn = wid & 3;
    const int gid = lane >> 2, tig = lane & 3;

    const int b = blockIdx.z;
    const float* Ab = Af + (long long)b * sA;
    const int T = Kd / BKH;
    const int m0 = blockIdx.y * 128;
    const int n0 = blockIdx.x * 128;

    DECLARE_FRAG_CONSTS

    float4 raf[8];
    float4 rb[4];

    auto loadTiles = [&](int kt) {
#pragma unroll
        for (int c = 0; c < 4; c++) {
            const int idx = tid + 256 * c;
            const int m = idx >> 3, f = idx & 7;
            const float* src = Ab + (size_t)(m0 + m) * lda + kt + f * 8;
            raf[2 * c]     = *(const float4*)src;
            raf[2 * c + 1] = *(const float4*)(src + 4);
        }
#pragma unroll
        for (int j = 0; j < 4; j++) {
            const int idx = tid + 256 * j;
            const int k = idx >> 4, c = idx & 15;
            rb[j] = *(const float4*)(Bb + (size_t)(kt + k) * ldb + n0 + c * 8);
        }
    };

    auto stsTiles = [&](int buf) {
        char* base = smc + buf * STAGE;
#pragma unroll
        for (int c = 0; c < 4; c++) {
            const int idx = tid + 256 * c;
            const int m = idx >> 3, f = idx & 7;
            __align__(16) __half2 hh[4];
            hh[0] = __floats2half2_rn(raf[2 * c].x, raf[2 * c].y);
            hh[1] = __floats2half2_rn(raf[2 * c].z, raf[2 * c].w);
            hh[2] = __floats2half2_rn(raf[2 * c + 1].x, raf[2 * c + 1].y);
            hh[3] = __floats2half2_rn(raf[2 * c + 1].z, raf[2 * c + 1].w);
            *(uint4*)(base + m * 128 + ((f ^ (m & 7)) << 4)) = *(const uint4*)hh;
        }
#pragma unroll
        for (int j = 0; j < 4; j++) {
            const int idx = tid + 256 * j;
            const int k = idx >> 4, c = idx & 15;
            *(uint4*)(base + ASTG + k * 256 + ((c ^ (k & 7)) << 4)) = *(const uint4*)&rb[j];
        }
    };

    float acc[4][4][4];
#pragma unroll
    for (int i = 0; i < 4; i++)
#pragma unroll
        for (int j = 0; j < 4; j++)
#pragma unroll
            for (int e = 0; e < 4; e++) acc[i][j][e] = 0.0f;

    loadTiles(0);
    stsTiles(0);
    __syncthreads();

    for (int it = 0; it < T; ++it) {
        const int cur = it & 1;
        if (it + 1 < T) loadTiles((it + 1) * BKH);

        const uint32_t Ab0 = sbase + (uint32_t)cur * STAGE + aByteBase;
        const uint32_t Bb0 = sbase + (uint32_t)cur * STAGE + ASTG + bRowByte;
        COMPUTE_STAGE(Ab0, Bb0);

        if (it + 1 < T) stsTiles((it + 1) & 1);
        __syncthreads();
    }

#pragma unroll
    for (int i = 0; i < 4; i++) {
        const int rbase = m0 + wm * 64 + i * 16 + gid;
#pragma unroll
        for (int j = 0; j < 4; j++) {
            const int cn = n0 + wn * 32 + j * 8 + tig * 2;
#pragma unroll
            for (int h = 0; h < 2; h++) {
                const int row = rbase + h * 8;
                float v0 = acc[i][j][2 * h + 0];
                float v1 = acc[i][j][2 * h + 1];
                if (EPI == 3 && cn < CD) {   // softmax numerator; |k|<~1.5, no max needed
                    v0 = expf(v0);
                    v1 = expf(v1);
                }
                __half2 hv = __floats2half2_rn(v0, v1);
                *(__half2*)(Cmat + (long long)b * sC + (size_t)row * ldc + cn) = hv;
            }
        }
    }
}

// ============ transposed-A fp16 GEMM: C[m][n] = sum_k A[k*lda+m] B[k*ldb+n] ====
template <int OUTH>
__global__ void __launch_bounds__(256)
hgemm_t(const __half* __restrict__ A, const __half* __restrict__ Bm,
        void* __restrict__ Cmat,
        int Kd, int nsplit, int lda, int ldb, int ldc,
        long long sA, long long sB, long long sC)
{
    extern __shared__ char smc[];
    const uint32_t sbase = (uint32_t)__cvta_generic_to_shared(smc);
    const int tid = threadIdx.x;
    const int wid = tid >> 5, lane = tid & 31;
    const int wm = wid >> 2, wn = wid & 3;
    const int gid = lane >> 2, tig = lane & 3;

    const int z = blockIdx.z;
    const int b = z / nsplit;
    const int s = z - b * nsplit;
    const __half* Ab = A + (long long)b * sA;
    const __half* Bb = Bm + (long long)b * sB;
    const int kChunk = Kd / nsplit;
    const int k0 = s * kChunk;
    const int T = kChunk / BKH;
    const int m0 = blockIdx.y * 128;
    const int n0 = blockIdx.x * 128;

    DECLARE_FRAG_CONSTS

    float4 ra[4], rb[4];

    auto loadTiles = [&](int kt) {
#pragma unroll
        for (int j = 0; j < 4; j++) {
            const int idx = tid + 256 * j;
            const int k = idx >> 4, mq = idx & 15;
            ra[j] = *(const float4*)(Ab + (size_t)(kt + k) * lda + m0 + mq * 8);
        }
#pragma unroll
        for (int j = 0; j < 4; j++) {
            const int idx = tid + 256 * j;
            const int k = idx >> 4, c = idx & 15;
            rb[j] = *(const float4*)(Bb + (size_t)(kt + k) * ldb + n0 + c * 8);
        }
    };

    auto stsTiles = [&](int buf) {
        char* base = smc + buf * STAGE;
#pragma unroll
        for (int j = 0; j < 4; j++) {
            const int idx = tid + 256 * j;
            const int k = idx >> 4, mq = idx & 15;
            const __half* hp = (const __half*)&ra[j];
#pragma unroll
            for (int e = 0; e < 8; e++) {
                const int m = mq * 8 + e;
                *(__half*)(base + m * 128 + (((k >> 3) ^ (m & 7)) << 4) + (k & 7) * 2) = hp[e];
            }
        }
#pragma unroll
        for (int j = 0; j < 4; j++) {
            const int idx = tid + 256 * j;
            const int k = idx >> 4, c = idx & 15;
            *(uint4*)(base + ASTG + k * 256 + ((c ^ (k & 7)) << 4)) = *(const uint4*)&rb[j];
        }
    };

    float acc[4][4][4];
#pragma unroll
    for (int i = 0; i < 4; i++)
#pragma unroll
        for (int j = 0; j < 4; j++)
#pragma unroll
            for (int e = 0; e < 4; e++) acc[i][j][e] = 0.0f;

    loadTiles(k0);
    stsTiles(0);
    __syncthreads();

    for (int it = 0; it < T; ++it) {
        const int cur = it & 1;
        if (it + 1 < T) loadTiles(k0 + (it + 1) * BKH);

        const uint32_t Ab0 = sbase + (uint32_t)cur * STAGE + aByteBase;
        const uint32_t Bb0 = sbase + (uint32_t)cur * STAGE + ASTG + bRowByte;
        COMPUTE_STAGE(Ab0, Bb0);

        if (it + 1 < T) stsTiles((it + 1) & 1);
        __syncthreads();
    }

#pragma unroll
    for (int i = 0; i < 4; i++) {
        const int rbase = m0 + wm * 64 + i * 16 + gid;
#pragma unroll
        for (int j = 0; j < 4; j++) {
            const int cn = n0 + wn * 32 + j * 8 + tig * 2;
#pragma unroll
            for (int h = 0; h < 2; h++) {
                const int row = rbase + h * 8;
                float v0 = acc[i][j][2 * h + 0];
                float v1 = acc[i][j][2 * h + 1];
                if (OUTH) {
                    __half2 hv = __floats2half2_rn(v0, v1);
                    *(__half2*)((__half*)Cmat + (long long)z * sC + (size_t)row * ldc + cn) = hv;
                } else {
                    float2 fv; fv.x = v0; fv.y = v1;
                    *(float2*)((float*)Cmat + (long long)z * sC + (size_t)row * ldc + cn) = fv;
                }
            }
        }
    }
}

// ---------------- fp32 -> fp16 converts ----------------
__device__ __forceinline__ void cvt8(const float4* in, __half* out, size_t i) {
    float4 u = in[2 * i], v = in[2 * i + 1];
    __align__(16) __half2 hh[4];
    hh[0] = __floats2half2_rn(u.x, u.y);
    hh[1] = __floats2half2_rn(u.z, u.w);
    hh[2] = __floats2half2_rn(v.x, v.y);
    hh[3] = __floats2half2_rn(v.z, v.w);
    *(uint4*)(out + i * 8) = *(const uint4*)hh;
}
__global__ void cvt1h(const float4* __restrict__ a, __half* __restrict__ ao, int n8)
{
    const int i = blockIdx.x * 256 + threadIdx.x;
    if (i >= n8) return;
    cvt8(a, ao, i);
}
__global__ void cvt4h(const float4* p0, __half* o0, const float4* p1, __half* o1,
                      const float4* p2, __half* o2, const float4* p3, __half* o3,
                      int n0, int n1, int n2, int n3)
{
    const int i = blockIdx.x * 256 + threadIdx.x;
    const float4* in; __half* out; int n;
    switch (blockIdx.y) {
        case 0: in = p0; out = o0; n = n0; break;
        case 1: in = p1; out = o1; n = n1; break;
        case 2: in = p2; out = o2; n = n2; break;
        default: in = p3; out = o3; n = n3; break;
    }
    if (i >= n) return;
    cvt8(in, out, i);
}
// interleave Wk|Wv into [k][512]
__global__ void cvt_kv(const float4* __restrict__ Wk, const float4* __restrict__ Wv,
                       __half* __restrict__ out, int n8)
{
    const int i = blockIdx.x * 256 + threadIdx.x;
    if (i >= n8) return;
    const float4* in = blockIdx.y ? Wv : Wk;
    const int ofs = blockIdx.y ? CD : 0;
    const int k = (i * 8) / CD, n = (i * 8) % CD;
    float4 u = in[2 * i], v = in[2 * i + 1];
    __align__(16) __half2 hh[4];
    hh[0] = __floats2half2_rn(u.x, u.y);
    hh[1] = __floats2half2_rn(u.z, u.w);
    hh[2] = __floats2half2_rn(v.x, v.y);
    hh[3] = __floats2half2_rn(v.z, v.w);
    *(uint4*)(out + (size_t)k * 512 + ofs + n) = *(const uint4*)hh;
}

// ---------------- column sums of exp(K) (KV cols 0-255, stride 512) ----------
__global__ void colsum_pass(const __half* __restrict__ KV, float* __restrict__ psum)
{
    const int b = blockIdx.x >> 3, cg = blockIdx.x & 7;
    const int seg = blockIdx.y;
    const int tx = threadIdx.x, ty = threadIdx.y;
    const int c = cg * 32 + tx;
    const __half* base = KV + (size_t)b * LD * 512 + c;
    __shared__ float red[32][33];
    float sum = 0.0f;
    const int l0 = seg * (LD / 8);
    for (int l = l0 + ty; l < l0 + LD / 8; l += 32)
        sum += __half2float(base[(size_t)l * 512]);
    red[ty][tx] = sum;
    __syncthreads();
    for (int s = 16; s > 0; s >>= 1) {
        if (ty < s) red[ty][tx] += red[ty + s][tx];
        __syncthreads();
    }
    if (ty == 0) psum[((size_t)b * CD + c) * 8 + seg] = red[0][tx];
}
__global__ void colsum_final(const float* __restrict__ psum, float* __restrict__ colsum)
{
    const int i = blockIdx.x * 256 + threadIdx.x;
    if (i >= BD * CD) return;
    float s = 0.0f;
#pragma unroll
    for (int p = 0; p < 8; p++) s += psum[(size_t)i * 8 + p];
    colsum[i] = s;
}

// ---------------- reduce split-K S partials; fold 1/colsum; fp16 out ---------
__global__ void s_reduce(const float* __restrict__ part,
                         const float* __restrict__ colsum,
                         __half* __restrict__ Sn)
{
    const int idx = blockIdx.x * 256 + threadIdx.x;
    const int b = idx / (CD * CD);
    const int de = idx - b * (CD * CD);
    const int e = de & (CD - 1);
    float s = 0.0f;
#pragma unroll
    for (int p = 0; p < NS; p++)
        s += part[((size_t)b * NS + p) * CD * CD + de];
    Sn[idx] = __float2half_rn(s / colsum[b * CD + e]);
}

// ---------------- row LayerNorm over C=256 ----------------
template <int INH, int OUTH>
__global__ void ln_rows(const void* __restrict__ X, const float* __restrict__ src,
                        const float* __restrict__ gamma, const float* __restrict__ beta,
                        void* __restrict__ out, int addRes)
{
    const int row = blockIdx.x * 8 + threadIdx.y;
    const int lane = threadIdx.x;

    float v[8];
#pragma unroll
    for (int i = 0; i < 8; i++) {
        const int c = lane + i * 32;
        v[i] = INH ? __half2float(((const __half*)X)[(size_t)row * CD + c])
                   : ((const float*)X)[(size_t)row * CD + c];
    }
    float s = 0.0f;
#pragma unroll
    for (int i = 0; i < 8; i++) s += v[i];
#pragma unroll
    for (int o = 16; o > 0; o >>= 1) s += __shfl_xor_sync(0xffffffffu, s, o);
    const float mu = s * (1.0f / CD);
    float q = 0.0f;
#pragma unroll
    for (int i = 0; i < 8; i++) { float d = v[i] - mu; q += d * d; }
#pragma unroll
    for (int o = 16; o > 0; o >>= 1) q += __shfl_xor_sync(0xffffffffu, q, o);
    const float rstd = rsqrtf(q * (1.0f / CD) + EPSL);
#pragma unroll
    for (int i = 0; i < 8; i++) {
        const int c = lane + i * 32;
        float y = (v[i] - mu) * rstd * gamma[c] + beta[c];
        if (addRes) y += src[(size_t)row * CD + c];
        if (OUTH) ((__half*)out)[(size_t)row * CD + c] = __float2half_rn(y);
        else      ((float*)out)[(size_t)row * CD + c] = y;
    }
}

// ---------------- launcher ----------------
extern "C" void kernel_launch(void* const* d_in, const int* in_sizes, int n_in,
                              void* d_out, int out_size)
{
    const float* source = (const float*)d_in[0];
    const float* target = (const float*)d_in[1];
    const float* Wq     = (const float*)d_in[2];
    const float* Wk     = (const float*)d_in[3];
    const float* Wv     = (const float*)d_in[4];
    const float* Wl     = (const float*)d_in[5];
    const float* gamma1 = (const float*)d_in[6];
    const float* beta1  = (const float*)d_in[7];
    const float* W1     = (const float*)d_in[8];
    const float* b1     = (const float*)d_in[9];
    const float* W2     = (const float*)d_in[10];
    const float* b2     = (const float*)d_in[11];
    const float* gamma2 = (const float*)d_in[12];
    const float* beta2  = (const float*)d_in[13];

    __half *srcH, *WqH, *WkvH, *WlH, *WqlH, *W1H, *W2H;
    __half *KVH, *SnH, *MmH, *attnH, *hidH;
    float *Spart, *colsum, *psum;
    cudaGetSymbolAddress((void**)&srcH, h_src);
    cudaGetSymbolAddress((void**)&WqH,  h_Wq);
    cudaGetSymbolAddress((void**)&WkvH, h_Wkv);
    cudaGetSymbolAddress((void**)&WlH,  h_Wl);
    cudaGetSymbolAddress((void**)&WqlH, h_Wql);
    cudaGetSymbolAddress((void**)&W1H,  h_W1);
    cudaGetSymbolAddress((void**)&W2H,  h_W2);
    cudaGetSymbolAddress((void**)&KVH,  h_KV);
    cudaGetSymbolAddress((void**)&SnH,  h_Sn);
    cudaGetSymbolAddress((void**)&MmH,  h_Mm);
    cudaGetSymbolAddress((void**)&attnH, h_attn);
    cudaGetSymbolAddress((void**)&hidH, h_hidden);
    cudaGetSymbolAddress((void**)&Spart, g_Spart);
    cudaGetSymbolAddress((void**)&colsum, g_colsum);
    cudaGetSymbolAddress((void**)&psum, g_psum);

    cudaFuncSetAttribute(hgemm_async<0, 0, 1>, cudaFuncAttributeMaxDynamicSharedMemorySize, SMEM_ASYNC);
    cudaFuncSetAttribute(hgemm_async<2, 2, 1>, cudaFuncAttributeMaxDynamicSharedMemorySize, SMEM_ASYNC);
    cudaFuncSetAttribute(hgemm_async<0, 1, 1>, cudaFuncAttributeMaxDynamicSharedMemorySize, SMEM_ASYNC);
    cudaFuncSetAttribute(hgemm_rm32<3>, cudaFuncAttributeMaxDynamicSharedMemorySize, SMEM_T);
    cudaFuncSetAttribute(hgemm_t<0>, cudaFuncAttributeMaxDynamicSharedMemorySize, SMEM_T);
    cudaFuncSetAttribute(hgemm_t<1>, cudaFuncAttributeMaxDynamicSharedMemorySize, SMEM_T);

    const long long LC = (long long)LD * CD;
    const long long L5 = (long long)LD * 512;
    const long long CC = (long long)CD * CD;
    const int NLC = BD * LD * CD;

    // 0) fp16 converts (source + weights only; target converted inside KV GEMM)
    cvt1h<<<NLC / 8 / 256, 256>>>((const float4*)source, srcH, NLC / 8);
    cvt4h<<<dim3(2 * CD * HID / 8 / 256, 4), 256>>>(
        (const float4*)Wq, WqH, (const float4*)Wl, WlH,
        (const float4*)W1, W1H, (const float4*)W2, W2H,
        CD * CD / 8, CD * CD / 8, 2 * CD * HID / 8, HID * CD / 8);
    cvt_kv<<<dim3(CD * CD / 8 / 256, 2), 256>>>((const float4*)Wk, (const float4*)Wv,
                                                WkvH, CD * CD / 8);

    // 1) Wql = Wq @ Wl  (256x256x256, fp16)
    hgemm_async<0, 0, 1><<<dim3(2, 2, 1), 256, SMEM_ASYNC>>>(WqH, nullptr, WlH, nullptr, WqlH,
                                                             CD, CD, CD, CD, 0, 0, 0);

    // 2) K|V fused projection straight from fp32 target; exp() fused on K half
    hgemm_rm32<3><<<dim3(4, 256 / 4 * BD, 1), 256, SMEM_T>>>(target, WkvH, KVH,
                                                             CD, CD, 512, 512, 0, 0);
    // NOTE: grid.y covers all batches contiguously: target is [B*L, C] row-major and
    // KV is [B*L, 512]; m is global row index, so z=0 with 256 y-tiles works:
    // (4, 256, 1) == (4, 64*BD, 1).

    // 3) column sums of exp(K)
    colsum_pass<<<dim3(32, 8), dim3(32, 32)>>>(KVH, psum);
    colsum_final<<<(BD * CD + 255) / 256, 256>>>(psum, colsum);

    // 4) S partials: Spart[b][s] = src^T(chunk) @ expK  (fp32 out)
    hgemm_t<0><<<dim3(2, 2, BD * NS), 256, SMEM_T>>>(srcH, KVH, Spart,
                                                     LD, NS, CD, 512, CD, LC, L5, CC);

    // 5) Sn = (sum partials) / colsum  -> fp16
    s_reduce<<<BD * CD * CD / 256, 256>>>(Spart, colsum, SnH);

    // 6) Mm = Sn^T @ Wql (fp16 out)
    hgemm_t<1><<<dim3(2, 2, BD), 256, SMEM_T>>>(SnH, WqlH, MmH,
                                                CD, 1, CD, CD, CD, CC, 0, CC);

    // 7) attn = V @ Mm (V = KV cols 256-511; fp16 out)
    hgemm_async<0, 0, 1><<<dim3(2, 64, BD), 256, SMEM_ASYNC>>>(KVH + CD, nullptr, MmH, nullptr, attnH,
                                                               CD, 512, CD, CD, L5, CC, LC);

    // 8) message = LN(attn), fp16 in/out in place
    ln_rows<1, 1><<<BD * LD / 8, dim3(32, 8)>>>(attnH, nullptr, gamma1, beta1, attnH, 0);

    // 9) hidden = gelu([srcH, message] @ W1 + b1), fp16 out
    hgemm_async<2, 2, 1><<<dim3(16, 256, 1), 256, SMEM_ASYNC>>>(srcH, attnH, W1H, b1, hidH,
                                                                2 * CD, CD, HID, HID, 0, 0, 0);

    // 10) tmp2 = hidden @ W2 + b2 -> fp16, reusing attn buffer (attn is dead now)
    hgemm_async<0, 1, 1><<<dim3(2, 256, 1), 256, SMEM_ASYNC>>>(hidH, nullptr, W2H, b2, attnH,
                                                               HID, HID, CD, CD, 0, 0, 0);

    // 11) out = source + LN(tmp2 fp16), fp32
    ln_rows<1, 0><<<BD * LD / 8, dim3(32, 8)>>>(attnH, source, gamma2, beta2,
                                                (float*)d_out, 1);
}

// round 14
// speedup vs baseline: 1.5745x; 1.5745x over previous
#include <cuda_runtime.h>
#include <cuda_fp16.h>
#include <math.h>
#include <stdint.h>

// Problem constants
#define BD   4
#define LD   8192
#define CD   256
#define HID  2048
#define NS   8
#define EPSL 1e-5f

// ---------------- scratch (__device__ globals; no allocations) ----------------
__device__ __align__(16) __half h_src[BD * LD * CD];
__device__ __align__(16) __half h_tgt[BD * LD * CD];
__device__ __align__(16) __half h_Wq[CD * CD];
__device__ __align__(16) __half h_Wkv[CD * 2 * CD];     // interleaved [k][Wk|Wv]
__device__ __align__(16) __half h_Wl[CD * CD];
__device__ __align__(16) __half h_Wql[CD * CD];         // Wq @ Wl
__device__ __align__(16) __half h_W1[2 * CD * HID];
__device__ __align__(16) __half h_W2[HID * CD];
__device__ __align__(16) __half h_KV[BD * LD * 2 * CD]; // cols 0-255 exp(K), 256-511 V
__device__ __align__(16) __half h_Sn[BD * CD * CD];
__device__ __align__(16) __half h_Mm[BD * CD * CD];
__device__ __align__(16) __half h_attn[BD * LD * CD];   // reused as fp16 tmp2 after FFN1
__device__ __align__(16) __half h_hidden[BD * LD * HID];
__device__ float g_Spart[BD * NS * CD * CD];
__device__ float g_colsum[BD * CD];
__device__ float g_psum[BD * CD * 8];

// ---------------- helpers ----------------
__device__ __forceinline__ void mma_f16(float* c, const uint32_t* a, const uint32_t* b) {
    asm volatile(
        "mma.sync.aligned.m16n8k16.row.col.f32.f16.f16.f32 "
        "{%0,%1,%2,%3}, {%4,%5,%6,%7}, {%8,%9}, {%0,%1,%2,%3};"
        : "+f"(c[0]), "+f"(c[1]), "+f"(c[2]), "+f"(c[3])
        : "r"(a[0]), "r"(a[1]), "r"(a[2]), "r"(a[3]), "r"(b[0]), "r"(b[1]));
}
__device__ __forceinline__ void ldsm4(uint32_t* r, uint32_t a) {
    asm volatile("ldmatrix.sync.aligned.m8n8.x4.shared.b16 {%0,%1,%2,%3}, [%4];"
                 : "=r"(r[0]), "=r"(r[1]), "=r"(r[2]), "=r"(r[3]) : "r"(a));
}
__device__ __forceinline__ void ldsm4t(uint32_t* r, uint32_t a) {
    asm volatile("ldmatrix.sync.aligned.m8n8.x4.trans.shared.b16 {%0,%1,%2,%3}, [%4];"
                 : "=r"(r[0]), "=r"(r[1]), "=r"(r[2]), "=r"(r[3]) : "r"(a));
}
__device__ __forceinline__ void cpasync16(uint32_t dst, const void* src) {
    asm volatile("cp.async.cg.shared.global [%0], [%1], 16;" :: "r"(dst), "l"(src));
}
__device__ __forceinline__ void cp_commit() {
    asm volatile("cp.async.commit_group;" ::: "memory");
}

// ---------------- fp16 GEMM tiling ----------------
// CTA tile 128x128x64; 8 warps (2 m x 4 n), warp tile 64x32.
// SMEM (halves), 16B-chunk xor swizzle, all LDSM/STS conflict-free:
//   A: byte(m,k) = m*128 + (((k/8) ^ (m&7))*16 + (k&7)*2)   (128 rows x 64 k)
//   B: byte(k,n) = k*256 + (((n/8) ^ (k&7))*16 + (n&7)*2)   (64 k-rows x 128 n)
#define BKH 64
#define ASTG 16384
#define STAGE 32768
#define SMEM_ASYNC (3 * STAGE)    // 98304
#define SMEM_T     (2 * STAGE)    // 65536

// Pipelined compute over one 64-k smem stage (8 warps). bf double-buffered.
#define COMPUTE_STAGE(Ab0, Bb0)                                                 \
    do {                                                                        \
        uint32_t bf[2][8];                                                      \
        ldsm4t(bf[0],     (Bb0) + bXor0);                                       \
        ldsm4t(bf[0] + 4, (Bb0) + bXor1);                                       \
        _Pragma("unroll")                                                       \
        for (int st = 0; st < 4; st++) {                                        \
            uint32_t af[4][4];                                                  \
            _Pragma("unroll")                                                   \
            for (int i = 0; i < 4; i++)                                         \
                ldsm4(af[i], (Ab0) + i * 2048 +                                 \
                      ((((uint32_t)st * 2 + aSel) ^ aXor) << 4));               \
            if (st < 3) {                                                       \
                ldsm4t(bf[(st + 1) & 1],     (Bb0) + (st + 1) * 4096 + bXor0);  \
                ldsm4t(bf[(st + 1) & 1] + 4, (Bb0) + (st + 1) * 4096 + bXor1);  \
            }                                                                   \
            const uint32_t* bc = bf[st & 1];                                    \
            _Pragma("unroll")                                                   \
            for (int i = 0; i < 4; i++) {                                       \
                mma_f16(acc[i][0], af[i], bc);                                  \
                mma_f16(acc[i][1], af[i], bc + 2);                              \
                mma_f16(acc[i][2], af[i], bc + 4);                              \
                mma_f16(acc[i][3], af[i], bc + 6);                              \
            }                                                                   \
        }                                                                       \
    } while (0)

#define DECLARE_FRAG_CONSTS                                                     \
    const uint32_t aRow = lane & 15, aSel = lane >> 4, aXor = aRow & 7;         \
    const uint32_t aByteBase = (uint32_t)(wm * 64 + aRow) * 128;                \
    const uint32_t r8 = lane & 7, g8 = lane >> 3;                               \
    const uint32_t bRowByte = ((g8 & 1) * 8 + r8) * 256;                        \
    const uint32_t bXor0 = (((uint32_t)wn * 4 + (g8 >> 1)) ^ r8) << 4;          \
    const uint32_t bXor1 = (((uint32_t)wn * 4 + 2 + (g8 >> 1)) ^ r8) << 4;

// ============ cp.async pipelined fp16 GEMM (A row-major / concat) ============
// EPI: 0 store; 1 +bias; 2 +bias+GELU; 3 exp() on columns < CD (K softmax numerator).
// OUTH: 1 = __half out, 0 = float out.
template <int AMODE, int EPI, int OUTH>
__global__ void __launch_bounds__(256, 2)
hgemm_async(const __half* __restrict__ A, const __half* __restrict__ A2,
            const __half* __restrict__ Bm, const float* __restrict__ bias,
            void* __restrict__ Cmat,
            int Kd, int lda, int ldb, int ldc,
            long long sA, long long sB, long long sC)
{
    extern __shared__ char smc[];
    const uint32_t sbase = (uint32_t)__cvta_generic_to_shared(smc);
    const int tid = threadIdx.x;
    const int wid = tid >> 5, lane = tid & 31;
    const int wm = wid >> 2, wn = wid & 3;
    const int gid = lane >> 2, tig = lane & 3;

    const int b = blockIdx.z;
    const __half* Ab = A + (long long)b * sA;
    const __half* Bb = Bm + (long long)b * sB;
    const int T = Kd / BKH;
    const int m0 = blockIdx.y * 128;
    const int n0 = blockIdx.x * 128;

    DECLARE_FRAG_CONSTS

    auto issue = [&](int it) {
        const uint32_t Abase = sbase + (uint32_t)(it % 3) * STAGE;
        const uint32_t Bbase = Abase + ASTG;
        const int kt = it * BKH;
#pragma unroll
        for (int j = 0; j < 4; j++) {
            const int idx = tid + 256 * j;
            const int m = idx >> 3, f = idx & 7;
            const int kk = kt + f * 8;
            const __half* src;
            if (AMODE == 2)
                src = (kk < CD) ? Ab + (size_t)(m0 + m) * CD + kk
                                : A2 + (size_t)(m0 + m) * CD + (kk - CD);
            else
                src = Ab + (size_t)(m0 + m) * lda + kk;
            cpasync16(Abase + (uint32_t)(m * 128 + ((f ^ (m & 7)) << 4)), src);
        }
#pragma unroll
        for (int j = 0; j < 4; j++) {
            const int idx = tid + 256 * j;
            const int k = idx >> 4, c = idx & 15;
            const __half* src = Bb + (size_t)(kt + k) * ldb + n0 + c * 8;
            cpasync16(Bbase + (uint32_t)(k * 256 + ((c ^ (k & 7)) << 4)), src);
        }
        cp_commit();
    };

    float acc[4][4][4];
#pragma unroll
    for (int i = 0; i < 4; i++)
#pragma unroll
        for (int j = 0; j < 4; j++)
#pragma unroll
            for (int e = 0; e < 4; e++) acc[i][j][e] = 0.0f;

    issue(0);
    if (T > 1) issue(1);

    for (int it = 0; it < T; ++it) {
        if (it + 1 < T) asm volatile("cp.async.wait_group 1;" ::: "memory");
        else            asm volatile("cp.async.wait_group 0;" ::: "memory");
        __syncthreads();
        if (it + 2 < T) issue(it + 2);

        const uint32_t Ab0 = sbase + (uint32_t)(it % 3) * STAGE + aByteBase;
        const uint32_t Bb0 = sbase + (uint32_t)(it % 3) * STAGE + ASTG + bRowByte;
        COMPUTE_STAGE(Ab0, Bb0);
    }

    // ---- epilogue ----
#pragma unroll
    for (int i = 0; i < 4; i++) {
        const int rbase = m0 + wm * 64 + i * 16 + gid;
#pragma unroll
        for (int j = 0; j < 4; j++) {
            const int cn = n0 + wn * 32 + j * 8 + tig * 2;
            float bia0 = 0.f, bia1 = 0.f;
            if (EPI == 1 || EPI == 2) { bia0 = bias[cn]; bia1 = bias[cn + 1]; }
#pragma unroll
            for (int h = 0; h < 2; h++) {
                const int row = rbase + h * 8;
                float v0 = acc[i][j][2 * h + 0] + bia0;
                float v1 = acc[i][j][2 * h + 1] + bia1;
                if (EPI == 2) {
                    v0 = 0.5f * v0 * (1.0f + erff(v0 * 0.70710678118654752f));
                    v1 = 0.5f * v1 * (1.0f + erff(v1 * 0.70710678118654752f));
                }
                if (EPI == 3 && cn < CD) {   // K half: softmax numerator (no max needed;
                    v0 = expf(v0);           // |k| <~ 1.5 with these weight scales)
                    v1 = expf(v1);
                }
                if (OUTH) {
                    __half2 hv = __floats2half2_rn(v0, v1);
                    *(__half2*)((__half*)Cmat + (long long)b * sC + (size_t)row * ldc + cn) = hv;
                } else {
                    float2 fv; fv.x = v0; fv.y = v1;
                    *(float2*)((float*)Cmat + (long long)b * sC + (size_t)row * ldc + cn) = fv;
                }
            }
        }
    }
}

// ============ transposed-A fp16 GEMM: C[m][n] = sum_k A[k*lda+m] B[k*ldb+n] ====
template <int OUTH>
__global__ void __launch_bounds__(256)
hgemm_t(const __half* __restrict__ A, const __half* __restrict__ Bm,
        void* __restrict__ Cmat,
        int Kd, int nsplit, int lda, int ldb, int ldc,
        long long sA, long long sB, long long sC)
{
    extern __shared__ char smc[];
    const uint32_t sbase = (uint32_t)__cvta_generic_to_shared(smc);
    const int tid = threadIdx.x;
    const int wid = tid >> 5, lane = tid & 31;
    const int wm = wid >> 2, wn = wid & 3;
    const int gid = lane >> 2, tig = lane & 3;

    const int z = blockIdx.z;
    const int b = z / nsplit;
    const int s = z - b * nsplit;
    const __half* Ab = A + (long long)b * sA;
    const __half* Bb = Bm + (long long)b * sB;
    const int kChunk = Kd / nsplit;
    const int k0 = s * kChunk;
    const int T = kChunk / BKH;
    const int m0 = blockIdx.y * 128;
    const int n0 = blockIdx.x * 128;

    DECLARE_FRAG_CONSTS

    float4 ra[4], rb[4];

    auto loadTiles = [&](int kt) {
#pragma unroll
        for (int j = 0; j < 4; j++) {
            const int idx = tid + 256 * j;
            const int k = idx >> 4, mq = idx & 15;
            ra[j] = *(const float4*)(Ab + (size_t)(kt + k) * lda + m0 + mq * 8);
        }
#pragma unroll
        for (int j = 0; j < 4; j++) {
            const int idx = tid + 256 * j;
            const int k = idx >> 4, c = idx & 15;
            rb[j] = *(const float4*)(Bb + (size_t)(kt + k) * ldb + n0 + c * 8);
        }
    };

    auto stsTiles = [&](int buf) {
        char* base = smc + buf * STAGE;
#pragma unroll
        for (int j = 0; j < 4; j++) {
            const int idx = tid + 256 * j;
            const int k = idx >> 4, mq = idx & 15;
            const __half* hp = (const __half*)&ra[j];
#pragma unroll
            for (int e = 0; e < 8; e++) {
                const int m = mq * 8 + e;
                *(__half*)(base + m * 128 + (((k >> 3) ^ (m & 7)) << 4) + (k & 7) * 2) = hp[e];
            }
        }
#pragma unroll
        for (int j = 0; j < 4; j++) {
            const int idx = tid + 256 * j;
            const int k = idx >> 4, c = idx & 15;
            *(uint4*)(base + ASTG + k * 256 + ((c ^ (k & 7)) << 4)) = *(const uint4*)&rb[j];
        }
    };

    float acc[4][4][4];
#pragma unroll
    for (int i = 0; i < 4; i++)
#pragma unroll
        for (int j = 0; j < 4; j++)
#pragma unroll
            for (int e = 0; e < 4; e++) acc[i][j][e] = 0.0f;

    loadTiles(k0);
    stsTiles(0);
    __syncthreads();

    for (int it = 0; it < T; ++it) {
        const int cur = it & 1;
        if (it + 1 < T) loadTiles(k0 + (it + 1) * BKH);

        const uint32_t Ab0 = sbase + (uint32_t)cur * STAGE + aByteBase;
        const uint32_t Bb0 = sbase + (uint32_t)cur * STAGE + ASTG + bRowByte;
        COMPUTE_STAGE(Ab0, Bb0);

        if (it + 1 < T) stsTiles((it + 1) & 1);
        __syncthreads();
    }

#pragma unroll
    for (int i = 0; i < 4; i++) {
        const int rbase = m0 + wm * 64 + i * 16 + gid;
#pragma unroll
        for (int j = 0; j < 4; j++) {
            const int cn = n0 + wn * 32 + j * 8 + tig * 2;
#pragma unroll
            for (int h = 0; h < 2; h++) {
                const int row = rbase + h * 8;
                float v0 = acc[i][j][2 * h + 0];
                float v1 = acc[i][j][2 * h + 1];
                if (OUTH) {
                    __half2 hv = __floats2half2_rn(v0, v1);
                    *(__half2*)((__half*)Cmat + (long long)z * sC + (size_t)row * ldc + cn) = hv;
                } else {
                    float2 fv; fv.x = v0; fv.y = v1;
                    *(float2*)((float*)Cmat + (long long)z * sC + (size_t)row * ldc + cn) = fv;
                }
            }
        }
    }
}

// ---------------- fp32 -> fp16 converts ----------------
__device__ __forceinline__ void cvt8(const float4* in, __half* out, size_t i) {
    float4 u = in[2 * i], v = in[2 * i + 1];
    __align__(16) __half2 hh[4];
    hh[0] = __floats2half2_rn(u.x, u.y);
    hh[1] = __floats2half2_rn(u.z, u.w);
    hh[2] = __floats2half2_rn(v.x, v.y);
    hh[3] = __floats2half2_rn(v.z, v.w);
    *(uint4*)(out + i * 8) = *(const uint4*)hh;
}
__global__ void cvt2h(const float4* __restrict__ a, __half* __restrict__ ao,
                      const float4* __restrict__ b, __half* __restrict__ bo, int n8)
{
    const int i = blockIdx.x * 256 + threadIdx.x;
    if (i >= n8) return;
    cvt8(blockIdx.y ? b : a, blockIdx.y ? bo : ao, i);
}
__global__ void cvt4h(const float4* p0, __half* o0, const float4* p1, __half* o1,
                      const float4* p2, __half* o2, const float4* p3, __half* o3,
                      int n0, int n1, int n2, int n3)
{
    const int i = blockIdx.x * 256 + threadIdx.x;
    const float4* in; __half* out; int n;
    switch (blockIdx.y) {
        case 0: in = p0; out = o0; n = n0; break;
        case 1: in = p1; out = o1; n = n1; break;
        case 2: in = p2; out = o2; n = n2; break;
        default: in = p3; out = o3; n = n3; break;
    }
    if (i >= n) return;
    cvt8(in, out, i);
}
// interleave Wk|Wv into [k][512]
__global__ void cvt_kv(const float4* __restrict__ Wk, const float4* __restrict__ Wv,
                       __half* __restrict__ out, int n8)
{
    const int i = blockIdx.x * 256 + threadIdx.x;
    if (i >= n8) return;
    const float4* in = blockIdx.y ? Wv : Wk;
    const int ofs = blockIdx.y ? CD : 0;
    const int k = (i * 8) / CD, n = (i * 8) % CD;
    float4 u = in[2 * i], v = in[2 * i + 1];
    __align__(16) __half2 hh[4];
    hh[0] = __floats2half2_rn(u.x, u.y);
    hh[1] = __floats2half2_rn(u.z, u.w);
    hh[2] = __floats2half2_rn(v.x, v.y);
    hh[3] = __floats2half2_rn(v.z, v.w);
    *(uint4*)(out + (size_t)k * 512 + ofs + n) = *(const uint4*)hh;
}

// ---------------- column sums of exp(K) (KV cols 0-255, stride 512) ----------
__global__ void colsum_pass(const __half* __restrict__ KV, float* __restrict__ psum)
{
    const int b = blockIdx.x >> 3, cg = blockIdx.x & 7;
    const int seg = blockIdx.y;
    const int tx = threadIdx.x, ty = threadIdx.y;
    const int c = cg * 32 + tx;
    const __half* base = KV + (size_t)b * LD * 512 + c;
    __shared__ float red[32][33];
    float sum = 0.0f;
    const int l0 = seg * (LD / 8);
    for (int l = l0 + ty; l < l0 + LD / 8; l += 32)
        sum += __half2float(base[(size_t)l * 512]);
    red[ty][tx] = sum;
    __syncthreads();
    for (int s = 16; s > 0; s >>= 1) {
        if (ty < s) red[ty][tx] += red[ty + s][tx];
        __syncthreads();
    }
    if (ty == 0) psum[((size_t)b * CD + c) * 8 + seg] = red[0][tx];
}
__global__ void colsum_final(const float* __restrict__ psum, float* __restrict__ colsum)
{
    const int i = blockIdx.x * 256 + threadIdx.x;
    if (i >= BD * CD) return;
    float s = 0.0f;
#pragma unroll
    for (int p = 0; p < 8; p++) s += psum[(size_t)i * 8 + p];
    colsum[i] = s;
}

// ---------------- reduce split-K S partials; fold 1/colsum; fp16 out ---------
__global__ void s_reduce(const float* __restrict__ part,
                         const float* __restrict__ colsum,
                         __half* __restrict__ Sn)
{
    const int idx = blockIdx.x * 256 + threadIdx.x;
    const int b = idx / (CD * CD);
    const int de = idx - b * (CD * CD);
    const int e = de & (CD - 1);
    float s = 0.0f;
#pragma unroll
    for (int p = 0; p < NS; p++)
        s += part[((size_t)b * NS + p) * CD * CD + de];
    Sn[idx] = __float2half_rn(s / colsum[b * CD + e]);
}

// ---------------- row LayerNorm over C=256 ----------------
template <int INH, int OUTH>
__global__ void ln_rows(const void* __restrict__ X, const float* __restrict__ src,
                        const float* __restrict__ gamma, const float* __restrict__ beta,
                        void* __restrict__ out, int addRes)
{
    const int row = blockIdx.x * 8 + threadIdx.y;
    const int lane = threadIdx.x;

    float v[8];
#pragma unroll
    for (int i = 0; i < 8; i++) {
        const int c = lane + i * 32;
        v[i] = INH ? __half2float(((const __half*)X)[(size_t)row * CD + c])
                   : ((const float*)X)[(size_t)row * CD + c];
    }
    float s = 0.0f;
#pragma unroll
    for (int i = 0; i < 8; i++) s += v[i];
#pragma unroll
    for (int o = 16; o > 0; o >>= 1) s += __shfl_xor_sync(0xffffffffu, s, o);
    const float mu = s * (1.0f / CD);
    float q = 0.0f;
#pragma unroll
    for (int i = 0; i < 8; i++) { float d = v[i] - mu; q += d * d; }
#pragma unroll
    for (int o = 16; o > 0; o >>= 1) q += __shfl_xor_sync(0xffffffffu, q, o);
    const float rstd = rsqrtf(q * (1.0f / CD) + EPSL);
#pragma unroll
    for (int i = 0; i < 8; i++) {
        const int c = lane + i * 32;
        float y = (v[i] - mu) * rstd * gamma[c] + beta[c];
        if (addRes) y += src[(size_t)row * CD + c];
        if (OUTH) ((__half*)out)[(size_t)row * CD + c] = __float2half_rn(y);
        else      ((float*)out)[(size_t)row * CD + c] = y;
    }
}

// ---------------- launcher ----------------
extern "C" void kernel_launch(void* const* d_in, const int* in_sizes, int n_in,
                              void* d_out, int out_size)
{
    const float* source = (const float*)d_in[0];
    const float* target = (const float*)d_in[1];
    const float* Wq     = (const float*)d_in[2];
    const float* Wk     = (const float*)d_in[3];
    const float* Wv     = (const float*)d_in[4];
    const float* Wl     = (const float*)d_in[5];
    const float* gamma1 = (const float*)d_in[6];
    const float* beta1  = (const float*)d_in[7];
    const float* W1     = (const float*)d_in[8];
    const float* b1     = (const float*)d_in[9];
    const float* W2     = (const float*)d_in[10];
    const float* b2     = (const float*)d_in[11];
    const float* gamma2 = (const float*)d_in[12];
    const float* beta2  = (const float*)d_in[13];

    __half *srcH, *tgtH, *WqH, *WkvH, *WlH, *WqlH, *W1H, *W2H;
    __half *KVH, *SnH, *MmH, *attnH, *hidH;
    float *Spart, *colsum, *psum;
    cudaGetSymbolAddress((void**)&srcH, h_src);
    cudaGetSymbolAddress((void**)&tgtH, h_tgt);
    cudaGetSymbolAddress((void**)&WqH,  h_Wq);
    cudaGetSymbolAddress((void**)&WkvH, h_Wkv);
    cudaGetSymbolAddress((void**)&WlH,  h_Wl);
    cudaGetSymbolAddress((void**)&WqlH, h_Wql);
    cudaGetSymbolAddress((void**)&W1H,  h_W1);
    cudaGetSymbolAddress((void**)&W2H,  h_W2);
    cudaGetSymbolAddress((void**)&KVH,  h_KV);
    cudaGetSymbolAddress((void**)&SnH,  h_Sn);
    cudaGetSymbolAddress((void**)&MmH,  h_Mm);
    cudaGetSymbolAddress((void**)&attnH, h_attn);
    cudaGetSymbolAddress((void**)&hidH, h_hidden);
    cudaGetSymbolAddress((void**)&Spart, g_Spart);
    cudaGetSymbolAddress((void**)&colsum, g_colsum);
    cudaGetSymbolAddress((void**)&psum, g_psum);

    cudaFuncSetAttribute(hgemm_async<0, 0, 1>, cudaFuncAttributeMaxDynamicSharedMemorySize, SMEM_ASYNC);
    cudaFuncSetAttribute(hgemm_async<0, 3, 1>, cudaFuncAttributeMaxDynamicSharedMemorySize, SMEM_ASYNC);
    cudaFuncSetAttribute(hgemm_async<2, 2, 1>, cudaFuncAttributeMaxDynamicSharedMemorySize, SMEM_ASYNC);
    cudaFuncSetAttribute(hgemm_async<0, 1, 1>, cudaFuncAttributeMaxDynamicSharedMemorySize, SMEM_ASYNC);
    cudaFuncSetAttribute(hgemm_t<0>, cudaFuncAttributeMaxDynamicSharedMemorySize, SMEM_T);
    cudaFuncSetAttribute(hgemm_t<1>, cudaFuncAttributeMaxDynamicSharedMemorySize, SMEM_T);

    const long long LC = (long long)LD * CD;
    const long long L5 = (long long)LD * 512;
    const long long CC = (long long)CD * CD;
    const int NLC = BD * LD * CD;

    // 0) fp16 converts
    cvt2h<<<dim3(NLC / 8 / 256, 2), 256>>>((const float4*)source, srcH,
                                           (const float4*)target, tgtH, NLC / 8);
    cvt4h<<<dim3(2 * CD * HID / 8 / 256, 4), 256>>>(
        (const float4*)Wq, WqH, (const float4*)Wl, WlH,
        (const float4*)W1, W1H, (const float4*)W2, W2H,
        CD * CD / 8, CD * CD / 8, 2 * CD * HID / 8, HID * CD / 8);
    cvt_kv<<<dim3(CD * CD / 8 / 256, 2), 256>>>((const float4*)Wk, (const float4*)Wv,
                                                WkvH, CD * CD / 8);

    // 1) Wql = Wq @ Wl  (256x256x256, fp16)
    hgemm_async<0, 0, 1><<<dim3(2, 2, 1), 256, SMEM_ASYNC>>>(WqH, nullptr, WlH, nullptr, WqlH,
                                                             CD, CD, CD, CD, 0, 0, 0);

    // 2) K|V fused projection (M=32768, N=512, K=256); exp() fused on K half
    hgemm_async<0, 3, 1><<<dim3(4, 256, 1), 256, SMEM_ASYNC>>>(tgtH, nullptr, WkvH, nullptr, KVH,
                                                               CD, CD, 512, 512, 0, 0, 0);

    // 3) column sums of exp(K)
    colsum_pass<<<dim3(32, 8), dim3(32, 32)>>>(KVH, psum);
    colsum_final<<<(BD * CD + 255) / 256, 256>>>(psum, colsum);

    // 4) S partials: Spart[b][s] = src^T(chunk) @ expK  (fp32 out; Q GEMM eliminated)
    hgemm_t<0><<<dim3(2, 2, BD * NS), 256, SMEM_T>>>(srcH, KVH, Spart,
                                                     LD, NS, CD, 512, CD, LC, L5, CC);

    // 5) Sn = (sum partials) / colsum  -> fp16
    s_reduce<<<BD * CD * CD / 256, 256>>>(Spart, colsum, SnH);

    // 6) Mm = Sn^T @ Wql (fp16 out)
    hgemm_t<1><<<dim3(2, 2, BD), 256, SMEM_T>>>(SnH, WqlH, MmH,
                                                CD, 1, CD, CD, CD, CC, 0, CC);

    // 7) attn = V @ Mm (V = KV cols 256-511; fp16 out)
    hgemm_async<0, 0, 1><<<dim3(2, 64, BD), 256, SMEM_ASYNC>>>(KVH + CD, nullptr, MmH, nullptr, attnH,
                                                               CD, 512, CD, CD, L5, CC, LC);

    // 8) message = LN(attn), fp16 in/out in place
    ln_rows<1, 1><<<BD * LD / 8, dim3(32, 8)>>>(attnH, nullptr, gamma1, beta1, attnH, 0);

    // 9) hidden = gelu([srcH, message] @ W1 + b1), fp16 out
    hgemm_async<2, 2, 1><<<dim3(16, 256, 1), 256, SMEM_ASYNC>>>(srcH, attnH, W1H, b1, hidH,
                                                                2 * CD, CD, HID, HID, 0, 0, 0);

    // 10) tmp2 = hidden @ W2 + b2 -> fp16, reusing attn buffer (attn is dead now)
    hgemm_async<0, 1, 1><<<dim3(2, 256, 1), 256, SMEM_ASYNC>>>(hidH, nullptr, W2H, b2, attnH,
                                                               HID, HID, CD, CD, 0, 0, 0);

    // 11) out = source + LN(tmp2 fp16), fp32
    ln_rows<1, 0><<<BD * LD / 8, dim3(32, 8)>>>(attnH, source, gamma2, beta2,
                                                (float*)d_out, 1);
}